// round 4
// baseline (speedup 1.0000x reference)
#include <cuda_runtime.h>

#define IMG_H 512
#define IMG_W 512
#define BLOCK 64
#define CPT   4                  // 64 threads * 4 cols = 256-wide column strip
#define BANDS 9
#define CSPLIT 2                 // column strips per image row-band
#define STRIPW 256
#define RINGF (8 * 5 * STRIPW)   // 8-row ring, 5 quantities, 256 cols = 40 KB

__device__ float g_part[1024];
__device__ unsigned int g_count;

struct Row6 { float4 ia, im, ic, ta, tm, tc; };

__device__ __forceinline__ Row6 load_row(const float* __restrict__ ib,
                                         const float* __restrict__ tb,
                                         int L, int xg)
{
    Row6 r;
    const float4 z = make_float4(0.f, 0.f, 0.f, 0.f);
    r.ia = z; r.im = z; r.ic = z; r.ta = z; r.tm = z; r.tc = z;
    if ((unsigned)L < (unsigned)IMG_H) {
        const float* ri = ib + L * IMG_W + xg;
        const float* rt = tb + L * IMG_W + xg;
        if (xg > 0) {
            r.ia = *(const float4*)(ri - 4);
            float4 b = *(const float4*)(rt - 4);
            r.ta = make_float4(fmaf(b.x,.5f,.5f), fmaf(b.y,.5f,.5f), fmaf(b.z,.5f,.5f), fmaf(b.w,.5f,.5f));
        }
        {
            r.im = *(const float4*)ri;
            float4 b = *(const float4*)rt;
            r.tm = make_float4(fmaf(b.x,.5f,.5f), fmaf(b.y,.5f,.5f), fmaf(b.z,.5f,.5f), fmaf(b.w,.5f,.5f));
        }
        if (xg + 4 < IMG_W) {
            r.ic = *(const float4*)(ri + 4);
            float4 b = *(const float4*)(rt + 4);
            r.tc = make_float4(fmaf(b.x,.5f,.5f), fmaf(b.y,.5f,.5f), fmaf(b.z,.5f,.5f), fmaf(b.w,.5f,.5f));
        }
    }
    return r;
}

__global__ __launch_bounds__(BLOCK) void cc_main(
    const float* __restrict__ inp, const float* __restrict__ tgt,
    float* __restrict__ out, int rowsPerBand, int grid, double inv_total)
{
    extern __shared__ float ring[];
    __shared__ float  red[BLOCK];
    __shared__ double dred[BLOCK];
    __shared__ int    lastFlag;

    const int tid  = threadIdx.x;
    const int blk  = blockIdx.x;
    const int img  = blk / (BANDS * CSPLIT);
    const int rem  = blk - img * (BANDS * CSPLIT);
    const int band = rem / CSPLIT;
    const int cs   = rem - band * CSPLIT;
    const int r0   = band * rowsPerBand;
    const int nrows = min(rowsPerBand, IMG_H - r0);

    const float* __restrict__ ib = inp + (size_t)img * IMG_H * IMG_W;
    const float* __restrict__ tb = tgt + (size_t)img * IMG_H * IMG_W;
    const int x0 = tid * CPT;            // strip-local column
    const int xg = cs * STRIPW + x0;     // global column

    float S0[CPT], S1[CPT], S2[CPT], S3[CPT], S4[CPT];
#pragma unroll
    for (int c = 0; c < CPT; c++) { S0[c]=0.f; S1[c]=0.f; S2[c]=0.f; S3[c]=0.f; S4[c]=0.f; }

    float acc = 0.f;
    const float invk = 1.0f / 81.0f;
    const int Lend = r0 + nrows + 4;

    Row6 cur = load_row(ib, tb, r0 - 4, xg);

    for (int L = r0 - 4; L < Lend; L++) {
        Row6 nxt = load_row(ib, tb, L + 1, xg);   // prefetch next row

        float vi[12], vt[12];
        vi[0]=cur.ia.x; vi[1]=cur.ia.y; vi[2]=cur.ia.z; vi[3]=cur.ia.w;
        vi[4]=cur.im.x; vi[5]=cur.im.y; vi[6]=cur.im.z; vi[7]=cur.im.w;
        vi[8]=cur.ic.x; vi[9]=cur.ic.y; vi[10]=cur.ic.z; vi[11]=cur.ic.w;
        vt[0]=cur.ta.x; vt[1]=cur.ta.y; vt[2]=cur.ta.z; vt[3]=cur.ta.w;
        vt[4]=cur.tm.x; vt[5]=cur.tm.y; vt[6]=cur.tm.z; vt[7]=cur.tm.w;
        vt[8]=cur.tc.x; vt[9]=cur.tc.y; vt[10]=cur.tc.z; vt[11]=cur.tc.w;

        // horizontal 9-sums for the 5 quantities over CPT output columns
        float h0[CPT], h1[CPT], h2[CPT], h3[CPT], h4[CPT];
        {
            float a0=0.f, a1=0.f, a2=0.f, a3=0.f, a4=0.f;
#pragma unroll
            for (int i = 0; i < 9; i++) {
                float x = vi[i], t = vt[i];
                a0 += x; a1 += t;
                a2 = fmaf(x, x, a2);
                a3 = fmaf(t, t, a3);
                a4 = fmaf(x, t, a4);
            }
            h0[0]=a0; h1[0]=a1; h2[0]=a2; h3[0]=a3; h4[0]=a4;
#pragma unroll
            for (int c = 1; c < CPT; c++) {
                float ni = vi[c+8], oi = vi[c-1];
                float nt = vt[c+8], ot = vt[c-1];
                a0 += ni - oi;
                a1 += nt - ot;
                a2 = fmaf(ni, ni, fmaf(-oi, oi, a2));
                a3 = fmaf(nt, nt, fmaf(-ot, ot, a3));
                a4 = fmaf(ni, nt, fmaf(-oi, ot, a4));
                h0[c]=a0; h1[c]=a1; h2[c]=a2; h3[c]=a3; h4[c]=a4;
            }
        }

        float* slot = ring + ((L & 7) * 5) * STRIPW + x0;
        const bool emit = (L >= r0 + 4);

        float4 o0, o1, o2, o3, o4;
        if (emit) {               // read h(L-8) before overwriting
            o0 = *(float4*)(slot + 0*STRIPW);
            o1 = *(float4*)(slot + 1*STRIPW);
            o2 = *(float4*)(slot + 2*STRIPW);
            o3 = *(float4*)(slot + 3*STRIPW);
            o4 = *(float4*)(slot + 4*STRIPW);
        }
        *(float4*)(slot + 0*STRIPW) = make_float4(h0[0],h0[1],h0[2],h0[3]);
        *(float4*)(slot + 1*STRIPW) = make_float4(h1[0],h1[1],h1[2],h1[3]);
        *(float4*)(slot + 2*STRIPW) = make_float4(h2[0],h2[1],h2[2],h2[3]);
        *(float4*)(slot + 3*STRIPW) = make_float4(h3[0],h3[1],h3[2],h3[3]);
        *(float4*)(slot + 4*STRIPW) = make_float4(h4[0],h4[1],h4[2],h4[3]);

#pragma unroll
        for (int c = 0; c < CPT; c++) {
            S0[c]+=h0[c]; S1[c]+=h1[c]; S2[c]+=h2[c]; S3[c]+=h3[c]; S4[c]+=h4[c];
        }

        if (emit) {
#pragma unroll
            for (int c = 0; c < CPT; c++) {
                float u0 = S0[c] * invk;
                float u1 = S1[c] * invk;
                float cross = fmaf(-u0, S1[c], S4[c]);
                float tv    = fmaf(-u1, S1[c], S3[c]);
                float iv    = fmaf(-u0, S0[c], S2[c]);
                acc += __fdividef(cross * cross, fmaf(tv, iv, 1e-5f));
            }
            S0[0]-=o0.x; S0[1]-=o0.y; S0[2]-=o0.z; S0[3]-=o0.w;
            S1[0]-=o1.x; S1[1]-=o1.y; S1[2]-=o1.z; S1[3]-=o1.w;
            S2[0]-=o2.x; S2[1]-=o2.y; S2[2]-=o2.z; S2[3]-=o2.w;
            S3[0]-=o3.x; S3[1]-=o3.y; S3[2]-=o3.z; S3[3]-=o3.w;
            S4[0]-=o4.x; S4[1]-=o4.y; S4[2]-=o4.z; S4[3]-=o4.w;
        }
        cur = nxt;
    }

    // block reduction of partial cc sums
    red[tid] = acc;
    __syncthreads();
#pragma unroll
    for (int s = BLOCK / 2; s > 0; s >>= 1) {
        if (tid < s) red[tid] += red[tid + s];
        __syncthreads();
    }

    // fused deterministic last-CTA reduction
    if (tid == 0) {
        g_part[blk] = red[0];
        __threadfence();
        unsigned int done = atomicAdd(&g_count, 1u);
        lastFlag = (done == (unsigned)(grid - 1)) ? 1 : 0;
    }
    __syncthreads();

    if (lastFlag) {
        double s = 0.0;
        for (int i = tid; i < grid; i += BLOCK) s += (double)g_part[i];
        dred[tid] = s;
        __syncthreads();
#pragma unroll
        for (int k = BLOCK / 2; k > 0; k >>= 1) {
            if (tid < k) dred[tid] += dred[tid + k];
            __syncthreads();
        }
        if (tid == 0) {
            out[0] = (float)(-dred[0] * inv_total);
            g_count = 0;               // reset for next graph replay
        }
    }
}

extern "C" void kernel_launch(void* const* d_in, const int* in_sizes, int n_in,
                              void* d_out, int out_size)
{
    const float* inp = (const float*)d_in[0];
    const float* tgt = (const float*)d_in[1];
    long total = in_sizes[0];
    int B = (int)(total / (IMG_H * IMG_W));
    int rpb = (IMG_H + BANDS - 1) / BANDS;    // 57
    int grid = B * BANDS * CSPLIT;            // 576 for B=32

    size_t shmem = (size_t)RINGF * sizeof(float);   // 40 KB
    cudaFuncSetAttribute(cc_main, cudaFuncAttributeMaxDynamicSharedMemorySize, (int)shmem);

    double inv_total = 1.0 / ((double)B * IMG_H * IMG_W);
    cc_main<<<grid, BLOCK, shmem>>>(inp, tgt, (float*)d_out, rpb, grid, inv_total);
}

// round 5
// speedup vs baseline: 1.1201x; 1.1201x over previous
#include <cuda_runtime.h>
#include <cuda_fp16.h>

#define IMG_H 512
#define IMG_W 512
#define BLOCK 128
#define CPT   4                  // 128 threads * 4 cols = full 512 width
#define BANDS 16                 // 512/16 = 32 rows per band, exact

__device__ float g_part[1024];
__device__ unsigned int g_count;

struct Row6 { float4 ia, im, ic, ta, tm, tc; };

__device__ __forceinline__ Row6 load_row(const float* __restrict__ ib,
                                         const float* __restrict__ tb,
                                         int L, int x0)
{
    Row6 r;
    const float4 z = make_float4(0.f, 0.f, 0.f, 0.f);
    r.ia = z; r.im = z; r.ic = z; r.ta = z; r.tm = z; r.tc = z;
    if ((unsigned)L < (unsigned)IMG_H) {
        const float* ri = ib + L * IMG_W + x0;
        const float* rt = tb + L * IMG_W + x0;
        if (x0 > 0) {
            r.ia = *(const float4*)(ri - 4);
            float4 b = *(const float4*)(rt - 4);
            r.ta = make_float4(fmaf(b.x,.5f,.5f), fmaf(b.y,.5f,.5f), fmaf(b.z,.5f,.5f), fmaf(b.w,.5f,.5f));
        }
        {
            r.im = *(const float4*)ri;
            float4 b = *(const float4*)rt;
            r.tm = make_float4(fmaf(b.x,.5f,.5f), fmaf(b.y,.5f,.5f), fmaf(b.z,.5f,.5f), fmaf(b.w,.5f,.5f));
        }
        if (x0 + 4 < IMG_W) {
            r.ic = *(const float4*)(ri + 4);
            float4 b = *(const float4*)(rt + 4);
            r.tc = make_float4(fmaf(b.x,.5f,.5f), fmaf(b.y,.5f,.5f), fmaf(b.z,.5f,.5f), fmaf(b.w,.5f,.5f));
        }
    }
    return r;
}

// 16-byte packet of 4 half2 (8 halves)
struct H8 { __half2 a, b, c, d; };
struct H4 { __half2 a, b; };

__global__ __launch_bounds__(BLOCK) void cc_main(
    const float* __restrict__ inp, const float* __restrict__ tgt,
    float* __restrict__ out, int grid, double inv_total)
{
    // half2-packed h-ring: 8 rows x (5 quantities x 4 cols) halves per thread
    // ringA: h0,h1 pairs (16B/thread); ringB: h2,h3 (16B); ringC: h4 (8B) = 40KB
    extern __shared__ char sm[];
    H8* ringA = (H8*)sm;                         // 8*128 * 16B = 16 KB
    H8* ringB = (H8*)(sm + 8 * BLOCK * 16);      // 16 KB
    H4* ringC = (H4*)(sm + 2 * 8 * BLOCK * 16);  //  8 KB

    __shared__ float  red[BLOCK];
    __shared__ double dred[BLOCK];
    __shared__ int    lastFlag;

    const int tid  = threadIdx.x;
    const int blk  = blockIdx.x;
    const int img  = blk / BANDS;
    const int band = blk - img * BANDS;
    const int r0   = band * (IMG_H / BANDS);     // 32 rows per band

    const float* __restrict__ ib = inp + (size_t)img * IMG_H * IMG_W;
    const float* __restrict__ tb = tgt + (size_t)img * IMG_H * IMG_W;
    const int x0 = tid * CPT;

    float S0[CPT], S1[CPT], S2[CPT], S3[CPT], S4[CPT];
#pragma unroll
    for (int c = 0; c < CPT; c++) { S0[c]=0.f; S1[c]=0.f; S2[c]=0.f; S3[c]=0.f; S4[c]=0.f; }

    float acc = 0.f;
    const float invk = 1.0f / 81.0f;
    const int Lend = r0 + (IMG_H / BANDS) + 4;

    Row6 cur = load_row(ib, tb, r0 - 4, x0);

    for (int L = r0 - 4; L < Lend; L++) {
        Row6 nxt = load_row(ib, tb, L + 1, x0);   // prefetch next row

        float vi[12], vt[12];
        vi[0]=cur.ia.x; vi[1]=cur.ia.y; vi[2]=cur.ia.z; vi[3]=cur.ia.w;
        vi[4]=cur.im.x; vi[5]=cur.im.y; vi[6]=cur.im.z; vi[7]=cur.im.w;
        vi[8]=cur.ic.x; vi[9]=cur.ic.y; vi[10]=cur.ic.z; vi[11]=cur.ic.w;
        vt[0]=cur.ta.x; vt[1]=cur.ta.y; vt[2]=cur.ta.z; vt[3]=cur.ta.w;
        vt[4]=cur.tm.x; vt[5]=cur.tm.y; vt[6]=cur.tm.z; vt[7]=cur.tm.w;
        vt[8]=cur.tc.x; vt[9]=cur.tc.y; vt[10]=cur.tc.z; vt[11]=cur.tc.w;

        // horizontal 9-sums for the 5 quantities over CPT output columns
        float h0[CPT], h1[CPT], h2[CPT], h3[CPT], h4[CPT];
        {
            float a0=0.f, a1=0.f, a2=0.f, a3=0.f, a4=0.f;
#pragma unroll
            for (int i = 0; i < 9; i++) {
                float x = vi[i], t = vt[i];
                a0 += x; a1 += t;
                a2 = fmaf(x, x, a2);
                a3 = fmaf(t, t, a3);
                a4 = fmaf(x, t, a4);
            }
            h0[0]=a0; h1[0]=a1; h2[0]=a2; h3[0]=a3; h4[0]=a4;
#pragma unroll
            for (int c = 1; c < CPT; c++) {
                float ni = vi[c+8], oi = vi[c-1];
                float nt = vt[c+8], ot = vt[c-1];
                a0 += ni - oi;
                a1 += nt - ot;
                a2 = fmaf(ni, ni, fmaf(-oi, oi, a2));
                a3 = fmaf(nt, nt, fmaf(-ot, ot, a3));
                a4 = fmaf(ni, nt, fmaf(-oi, ot, a4));
                h0[c]=a0; h1[c]=a1; h2[c]=a2; h3[c]=a3; h4[c]=a4;
            }
        }

        const int slot = (L & 7) * BLOCK + tid;
        const bool emit = (L >= r0 + 4);

        H8 ra, rb; H4 rc;
        if (emit) {               // read packed h(L-8) before overwriting
            ra = ringA[slot];
            rb = ringB[slot];
            rc = ringC[slot];
        }
        // pack h(L) to half2 and store (16B-aligned, conflict-free)
        {
            H8 wa, wb; H4 wc;
            wa.a = __floats2half2_rn(h0[0], h0[1]);
            wa.b = __floats2half2_rn(h0[2], h0[3]);
            wa.c = __floats2half2_rn(h1[0], h1[1]);
            wa.d = __floats2half2_rn(h1[2], h1[3]);
            wb.a = __floats2half2_rn(h2[0], h2[1]);
            wb.b = __floats2half2_rn(h2[2], h2[3]);
            wb.c = __floats2half2_rn(h3[0], h3[1]);
            wb.d = __floats2half2_rn(h3[2], h3[3]);
            wc.a = __floats2half2_rn(h4[0], h4[1]);
            wc.b = __floats2half2_rn(h4[2], h4[3]);
            ringA[slot] = wa;
            ringB[slot] = wb;
            ringC[slot] = wc;
        }

        // vertical running sums += new row (exact fp32 h)
#pragma unroll
        for (int c = 0; c < CPT; c++) {
            S0[c]+=h0[c]; S1[c]+=h1[c]; S2[c]+=h2[c]; S3[c]+=h3[c]; S4[c]+=h4[c];
        }

        if (emit) {
            // output row y = L-4 : S holds rows [L-8, L]
#pragma unroll
            for (int c = 0; c < CPT; c++) {
                float u0 = S0[c] * invk;
                float u1 = S1[c] * invk;
                float cross = fmaf(-u0, S1[c], S4[c]);
                float tv    = fmaf(-u1, S1[c], S3[c]);
                float iv    = fmaf(-u0, S0[c], S2[c]);
                acc += __fdividef(cross * cross, fmaf(tv, iv, 1e-5f));
            }
            // subtract h(L-8) (unpack half2 -> float)
            float2 f;
            f = __half22float2(ra.a); S0[0]-=f.x; S0[1]-=f.y;
            f = __half22float2(ra.b); S0[2]-=f.x; S0[3]-=f.y;
            f = __half22float2(ra.c); S1[0]-=f.x; S1[1]-=f.y;
            f = __half22float2(ra.d); S1[2]-=f.x; S1[3]-=f.y;
            f = __half22float2(rb.a); S2[0]-=f.x; S2[1]-=f.y;
            f = __half22float2(rb.b); S2[2]-=f.x; S2[3]-=f.y;
            f = __half22float2(rb.c); S3[0]-=f.x; S3[1]-=f.y;
            f = __half22float2(rb.d); S3[2]-=f.x; S3[3]-=f.y;
            f = __half22float2(rc.a); S4[0]-=f.x; S4[1]-=f.y;
            f = __half22float2(rc.b); S4[2]-=f.x; S4[3]-=f.y;
        }
        cur = nxt;
    }

    // block reduction of partial cc sums
    red[tid] = acc;
    __syncthreads();
#pragma unroll
    for (int s = BLOCK / 2; s > 0; s >>= 1) {
        if (tid < s) red[tid] += red[tid + s];
        __syncthreads();
    }

    // fused deterministic last-CTA reduction
    if (tid == 0) {
        g_part[blk] = red[0];
        __threadfence();
        unsigned int done = atomicAdd(&g_count, 1u);
        lastFlag = (done == (unsigned)(grid - 1)) ? 1 : 0;
    }
    __syncthreads();

    if (lastFlag) {
        double s = 0.0;
        for (int i = tid; i < grid; i += BLOCK) s += (double)g_part[i];
        dred[tid] = s;
        __syncthreads();
#pragma unroll
        for (int k = BLOCK / 2; k > 0; k >>= 1) {
            if (tid < k) dred[tid] += dred[tid + k];
            __syncthreads();
        }
        if (tid == 0) {
            out[0] = (float)(-dred[0] * inv_total);
            g_count = 0;               // reset for next graph replay
        }
    }
}

extern "C" void kernel_launch(void* const* d_in, const int* in_sizes, int n_in,
                              void* d_out, int out_size)
{
    const float* inp = (const float*)d_in[0];
    const float* tgt = (const float*)d_in[1];
    long total = in_sizes[0];
    int B = (int)(total / (IMG_H * IMG_W));
    int grid = B * BANDS;                        // 512 for B=32

    size_t shmem = (size_t)(8 * BLOCK * (16 + 16 + 8));   // 40 KB
    cudaFuncSetAttribute(cc_main, cudaFuncAttributeMaxDynamicSharedMemorySize, (int)shmem);

    double inv_total = 1.0 / ((double)B * IMG_H * IMG_W);
    cc_main<<<grid, BLOCK, shmem>>>(inp, tgt, (float*)d_out, grid, inv_total);
}